// round 9
// baseline (speedup 1.0000x reference)
#include <cuda_runtime.h>

#define EPS_F 1e-5f
#define BDIM 128
#define CDIM 32
#define NA 12
#define NB 12
#define PDIM 8192

#define TPB 256
#define TILE_P 256
#define FPAD 13           // feature row stride (coprime with 32 -> conflict-free gather)
#define ASTR 260          // aggS row stride in floats (260%32=4 -> optimal 4-phase vec access; 16B aligned)

// Folded conv+bn weights, computed by prologue kernel each launch.
__device__ float g_wfold[CDIM * CDIM];
__device__ float g_bfold[CDIM];

// ---------------------------------------------------------------------------
// Prologue: fold bn1 + conv + bn2 into W', bias'
// ---------------------------------------------------------------------------
__global__ void fold_kernel(const float* __restrict__ w,
                            const float* __restrict__ g1, const float* __restrict__ b1,
                            const float* __restrict__ m1, const float* __restrict__ v1,
                            const float* __restrict__ g2, const float* __restrict__ b2,
                            const float* __restrict__ m2, const float* __restrict__ v2) {
    __shared__ float s1[CDIM], t1[CDIM], s2[CDIM], t2[CDIM];
    int t = threadIdx.x;
    if (t < CDIM) {
        float sc1 = g1[t] * rsqrtf(v1[t] + EPS_F);
        s1[t] = sc1;
        t1[t] = b1[t] - m1[t] * sc1;
        float sc2 = g2[t] * rsqrtf(v2[t] + EPS_F);
        s2[t] = sc2;
        t2[t] = b2[t] - m2[t] * sc2;
    }
    __syncthreads();
    if (t < CDIM * CDIM) {
        int o = t >> 5;
        int c = t & 31;
        g_wfold[t] = w[t] * s1[c] * s2[o];
    }
    if (t < CDIM) {
        int o = t;
        float s = 0.f;
        #pragma unroll
        for (int c = 0; c < CDIM; c++) s += w[o * CDIM + c] * t1[c];
        g_bfold[o] = s * s2[o] + t2[o];
    }
}

// ---------------------------------------------------------------------------
// Packed f32x2 helpers (sm_103a FFMA2 — ptxas never emits this from C++)
// ---------------------------------------------------------------------------
__device__ __forceinline__ unsigned long long pack2(float lo, float hi) {
    unsigned long long r;
    asm("mov.b64 %0, {%1, %2};" : "=l"(r) : "f"(lo), "f"(hi));
    return r;
}
__device__ __forceinline__ void unpack2(unsigned long long v, float& lo, float& hi) {
    asm("mov.b64 {%0, %1}, %2;" : "=f"(lo), "=f"(hi) : "l"(v));
}
__device__ __forceinline__ unsigned long long fma2(unsigned long long a,
                                                   unsigned long long b,
                                                   unsigned long long c) {
    unsigned long long d;
    asm("fma.rn.f32x2 %0, %1, %2, %3;" : "=l"(d) : "l"(a), "l"(b), "l"(c));
    return d;
}

// ---------------------------------------------------------------------------
// Main fused kernel.
// Phase 1 (c-parallel gather): lane = channel c, point uniform per warp step.
//   Feature rows padded to stride 13 => bank(13c+j) distinct across lanes
//   => every gather LDS is 1 wavefront (data floor).
// Phase 2 (register-tiled GEMM): thread tile 8 o x 4 n. Per c per warp:
//   4 warp-uniform weight LDS.128 (broadcast) + 1 agg LDS.128/lane (4 wf)
//   feeding 16 FFMA2.
// grid = (PDIM/TILE_P, BDIM); block = 256; 44KB smem -> 3 blocks/SM.
// ---------------------------------------------------------------------------
__global__ __launch_bounds__(TPB, 3) void feynnet_kernel(
    const float* __restrict__ feat_a, const float* __restrict__ feat_b,
    const int* __restrict__ assign_a, const int* __restrict__ assign_b,
    float* __restrict__ out) {
    __shared__ float faP[CDIM * FPAD];                // 1.6 KB padded
    __shared__ float fbP[CDIM * FPAD];                // 1.6 KB
    __shared__ unsigned long long w2t[CDIM * CDIM];   // [c][o] dup pairs, 8 KB
    __shared__ unsigned long long bias2[CDIM];
    __shared__ float aggS[CDIM * ASTR];               // [c][n] padded, 33.3 KB

    const int t = threadIdx.x;
    const int b = blockIdx.y;
    const int ptile = blockIdx.x * TILE_P;

    // ---- Phase 0: stage padded feats, transposed-dup weights, dup bias ----
    // NOTE: CDIM*NA = 384 > TPB, so these MUST be strided loops.
    for (int i = t; i < CDIM * NA; i += TPB) {
        int c = i / NA, j = i - c * NA;
        faP[c * FPAD + j] = feat_a[b * CDIM * NA + i];
    }
    for (int i = t; i < CDIM * NB; i += TPB) {
        int c = i / NB, j = i - c * NB;
        fbP[c * FPAD + j] = feat_b[b * CDIM * NB + i];
    }
    for (int i = t; i < CDIM * CDIM; i += TPB) {
        int c = i >> 5;
        int o = i & 31;
        float w = g_wfold[o * CDIM + c];
        w2t[i] = pack2(w, w);           // w2t[c*32+o] = (w[o][c], w[o][c])
    }
    if (t >= TPB - CDIM) {
        int o = t - (TPB - CDIM);
        float bb = g_bfold[o];
        bias2[o] = pack2(bb, bb);
    }
    __syncthreads();

    // ---- Phase 1: c-parallel gather + max-aggregate ----
    {
        const int wid = t >> 5;
        const int lane = t & 31;              // = channel c
        const int crow = lane * FPAD;
        float* aggRow = aggS + lane * ASTR;

        #pragma unroll
        for (int batch = 0; batch < 8; batch++) {
            const int p0 = wid * 32 + batch * 4;           // 4 points per step
            // warp-uniform index loads: assign rows for p0..p0+3 (M=2)
            const int4 qa0 = __ldg((const int4*)(assign_a + 2 * (ptile + p0)));
            const int4 qa1 = __ldg((const int4*)(assign_a + 2 * (ptile + p0) + 4));
            const int4 qb0 = __ldg((const int4*)(assign_b + 2 * (ptile + p0)));
            const int4 qb1 = __ldg((const int4*)(assign_b + 2 * (ptile + p0) + 4));

            float v0 = fmaxf(fmaxf(faP[crow + qa0.x], faP[crow + qa0.y]),
                             fmaxf(fbP[crow + qb0.x], fbP[crow + qb0.y]));
            float v1 = fmaxf(fmaxf(faP[crow + qa0.z], faP[crow + qa0.w]),
                             fmaxf(fbP[crow + qb0.z], fbP[crow + qb0.w]));
            float v2 = fmaxf(fmaxf(faP[crow + qa1.x], faP[crow + qa1.y]),
                             fmaxf(fbP[crow + qb1.x], fbP[crow + qb1.y]));
            float v3 = fmaxf(fmaxf(faP[crow + qa1.z], faP[crow + qa1.w]),
                             fmaxf(fbP[crow + qb1.z], fbP[crow + qb1.w]));

            *reinterpret_cast<float4*>(aggRow + p0) = make_float4(v0, v1, v2, v3);
        }
    }
    __syncthreads();

    // ---- Phase 2: register-tiled GEMM, thread tile 8 o x 4 n ----
    const int og = t >> 6;        // 0..3, warp-uniform -> broadcast weight loads
    const int ng = t & 63;        // 0..63, points 4ng..4ng+3
    const int o0 = og * 8;

    unsigned long long acc[8][2];
    #pragma unroll
    for (int o = 0; o < 8; o++) {
        unsigned long long bb = bias2[o0 + o];
        acc[o][0] = bb;
        acc[o][1] = bb;
    }

    #pragma unroll
    for (int c = 0; c < CDIM; c++) {
        const unsigned long long* wr = w2t + c * CDIM + o0;
        const ulonglong2 w01 = *reinterpret_cast<const ulonglong2*>(wr);
        const ulonglong2 w23 = *reinterpret_cast<const ulonglong2*>(wr + 2);
        const ulonglong2 w45 = *reinterpret_cast<const ulonglong2*>(wr + 4);
        const ulonglong2 w67 = *reinterpret_cast<const ulonglong2*>(wr + 6);
        const ulonglong2 a =
            *reinterpret_cast<const ulonglong2*>(aggS + c * ASTR + 4 * ng);

        acc[0][0] = fma2(w01.x, a.x, acc[0][0]);
        acc[0][1] = fma2(w01.x, a.y, acc[0][1]);
        acc[1][0] = fma2(w01.y, a.x, acc[1][0]);
        acc[1][1] = fma2(w01.y, a.y, acc[1][1]);
        acc[2][0] = fma2(w23.x, a.x, acc[2][0]);
        acc[2][1] = fma2(w23.x, a.y, acc[2][1]);
        acc[3][0] = fma2(w23.y, a.x, acc[3][0]);
        acc[3][1] = fma2(w23.y, a.y, acc[3][1]);
        acc[4][0] = fma2(w45.x, a.x, acc[4][0]);
        acc[4][1] = fma2(w45.x, a.y, acc[4][1]);
        acc[5][0] = fma2(w45.y, a.x, acc[5][0]);
        acc[5][1] = fma2(w45.y, a.y, acc[5][1]);
        acc[6][0] = fma2(w67.x, a.x, acc[6][0]);
        acc[6][1] = fma2(w67.x, a.y, acc[6][1]);
        acc[7][0] = fma2(w67.y, a.x, acc[7][0]);
        acc[7][1] = fma2(w67.y, a.y, acc[7][1]);
    }

    // ---- Epilogue: relu + coalesced float4 stores ----
    float* outb = out + (size_t)b * CDIM * PDIM + ptile + 4 * ng;
    #pragma unroll
    for (int o = 0; o < 8; o++) {
        float x0, x1, x2, x3;
        unpack2(acc[o][0], x0, x1);
        unpack2(acc[o][1], x2, x3);
        *reinterpret_cast<float4*>(outb + (size_t)(o0 + o) * PDIM) =
            make_float4(fmaxf(x0, 0.f), fmaxf(x1, 0.f),
                        fmaxf(x2, 0.f), fmaxf(x3, 0.f));
    }
}

// ---------------------------------------------------------------------------
// Launch
// ---------------------------------------------------------------------------
extern "C" void kernel_launch(void* const* d_in, const int* in_sizes, int n_in,
                              void* d_out, int out_size) {
    const float* feat_a = (const float*)d_in[0];
    const float* feat_b = (const float*)d_in[1];
    const int* assign_a = (const int*)d_in[2];
    const int* assign_b = (const int*)d_in[3];
    const float* bn1_gamma = (const float*)d_in[4];
    const float* bn1_beta = (const float*)d_in[5];
    const float* bn1_mean = (const float*)d_in[6];
    const float* bn1_var = (const float*)d_in[7];
    const float* conv_w = (const float*)d_in[8];
    const float* bn2_gamma = (const float*)d_in[9];
    const float* bn2_beta = (const float*)d_in[10];
    const float* bn2_mean = (const float*)d_in[11];
    const float* bn2_var = (const float*)d_in[12];
    float* out = (float*)d_out;

    fold_kernel<<<1, CDIM * CDIM>>>(conv_w, bn1_gamma, bn1_beta, bn1_mean, bn1_var,
                                    bn2_gamma, bn2_beta, bn2_mean, bn2_var);

    dim3 grid(PDIM / TILE_P, BDIM);
    feynnet_kernel<<<grid, TPB>>>(feat_a, feat_b, assign_a, assign_b, out);
}

// round 10
// speedup vs baseline: 1.0503x; 1.0503x over previous
#include <cuda_runtime.h>

#define EPS_F 1e-5f
#define BDIM 128
#define CDIM 32
#define NA 12
#define NB 12
#define PDIM 8192

#define TPB 128
#define TILE_P 256
#define FPAD 13           // feature row stride, coprime with 32 -> conflict-free gather
#define ASTR 260          // aggS row stride (260%32=4): 4-phase-perfect .128 access

// ---------------------------------------------------------------------------
// Packed f32x2 helpers (sm_103a FFMA2 — ptxas never emits this from C++)
// ---------------------------------------------------------------------------
__device__ __forceinline__ unsigned long long pack2(float lo, float hi) {
    unsigned long long r;
    asm("mov.b64 %0, {%1, %2};" : "=l"(r) : "f"(lo), "f"(hi));
    return r;
}
__device__ __forceinline__ void unpack2(unsigned long long v, float& lo, float& hi) {
    asm("mov.b64 {%0, %1}, %2;" : "=f"(lo), "=f"(hi) : "l"(v));
}
__device__ __forceinline__ unsigned long long fma2(unsigned long long a,
                                                   unsigned long long b,
                                                   unsigned long long c) {
    unsigned long long d;
    asm("fma.rn.f32x2 %0, %1, %2, %3;" : "=l"(d) : "l"(a), "l"(b), "l"(c));
    return d;
}

// ---------------------------------------------------------------------------
// Single fused kernel (fold done redundantly per block — removes a launch).
// Phase 1 (c-parallel gather): lane = channel; feature rows stride-13 padded
//   => every gather LDS is exactly 1 crossbar cycle.
// Phase 2 (register-tiled GEMM): thread tile 8o x 8n; warp = one o-group.
//   Per c per warp: 8 SCALAR broadcast weight LDS (1 cyc each, N=1) packed
//   to f32x2 via ALU movs + 2 agg LDS.128 (4 cyc, phase-perfect) feeding
//   32 FFMA2 -> crossbar 16 cyc vs FMA 64 SMSP-cyc across 4 warps: balanced.
// grid = (PDIM/TILE_P, BDIM); block = 128; smem ~41 KB static.
// ---------------------------------------------------------------------------
__global__ __launch_bounds__(TPB, 4) void feynnet_kernel(
    const float* __restrict__ feat_a, const float* __restrict__ feat_b,
    const int* __restrict__ assign_a, const int* __restrict__ assign_b,
    const float* __restrict__ conv_w,
    const float* __restrict__ g1, const float* __restrict__ b1,
    const float* __restrict__ m1, const float* __restrict__ v1,
    const float* __restrict__ g2, const float* __restrict__ b2,
    const float* __restrict__ m2, const float* __restrict__ v2,
    float* __restrict__ out) {
    __shared__ float s1[CDIM], t1v[CDIM], s2[CDIM], t2v[CDIM];
    __shared__ float faP[CDIM * FPAD];     // 1.6 KB padded
    __shared__ float fbP[CDIM * FPAD];     // 1.6 KB
    __shared__ float wS[CDIM * CDIM];      // folded, [c][o], 4 KB
    __shared__ float biasS[CDIM];
    __shared__ float aggS[CDIM * ASTR];    // [c][point] padded, 33.3 KB

    const int t = threadIdx.x;
    const int b = blockIdx.y;
    const int ptile = blockIdx.x * TILE_P;

    // ---- Phase 0a: bn scales ----
    if (t < CDIM) {
        float sc1 = g1[t] * rsqrtf(v1[t] + EPS_F);
        s1[t] = sc1;
        t1v[t] = b1[t] - m1[t] * sc1;
        float sc2 = g2[t] * rsqrtf(v2[t] + EPS_F);
        s2[t] = sc2;
        t2v[t] = b2[t] - m2[t] * sc2;
    }
    __syncthreads();

    // ---- Phase 0b: folded weights [c][o], bias, padded feats ----
    for (int i = t; i < CDIM * CDIM; i += TPB) {
        int o = i >> 5, c = i & 31;
        wS[c * CDIM + o] = conv_w[i] * s1[c] * s2[o];
    }
    if (t < CDIM) {
        int o = t;
        float s = 0.f;
        #pragma unroll
        for (int c = 0; c < CDIM; c++) s += conv_w[o * CDIM + c] * t1v[c];
        biasS[o] = s * s2[o] + t2v[o];
    }
    for (int i = t; i < CDIM * NA; i += TPB) {        // 384 > TPB: strided!
        int c = i / NA, j = i - c * NA;
        faP[c * FPAD + j] = feat_a[b * CDIM * NA + i];
    }
    for (int i = t; i < CDIM * NB; i += TPB) {
        int c = i / NB, j = i - c * NB;
        fbP[c * FPAD + j] = feat_b[b * CDIM * NB + i];
    }
    __syncthreads();

    // ---- Phase 1: c-parallel gather + max (warp w -> points [64w, 64w+64)) ----
    {
        const int wid = t >> 5;
        const int lane = t & 31;               // = channel c
        const int crow = lane * FPAD;
        float* aggRow = aggS + lane * ASTR;

        #pragma unroll
        for (int step = 0; step < 16; step++) {
            const int p0 = wid * 64 + step * 4;          // 4 points per step
            const int4 qa0 = __ldg((const int4*)(assign_a + 2 * (ptile + p0)));
            const int4 qa1 = __ldg((const int4*)(assign_a + 2 * (ptile + p0) + 4));
            const int4 qb0 = __ldg((const int4*)(assign_b + 2 * (ptile + p0)));
            const int4 qb1 = __ldg((const int4*)(assign_b + 2 * (ptile + p0) + 4));

            float v0 = fmaxf(fmaxf(faP[crow + qa0.x], faP[crow + qa0.y]),
                             fmaxf(fbP[crow + qb0.x], fbP[crow + qb0.y]));
            float v1 = fmaxf(fmaxf(faP[crow + qa0.z], faP[crow + qa0.w]),
                             fmaxf(fbP[crow + qb0.z], fbP[crow + qb0.w]));
            float v2 = fmaxf(fmaxf(faP[crow + qa1.x], faP[crow + qa1.y]),
                             fmaxf(fbP[crow + qb1.x], fbP[crow + qb1.y]));
            float v3 = fmaxf(fmaxf(faP[crow + qa1.z], faP[crow + qa1.w]),
                             fmaxf(fbP[crow + qb1.z], fbP[crow + qb1.w]));

            *reinterpret_cast<float4*>(aggRow + p0) = make_float4(v0, v1, v2, v3);
        }
    }
    __syncthreads();

    // ---- Phase 2: register-tiled GEMM, thread tile 8 o x 8 n ----
    const int og = t >> 5;        // warp id == o-group -> warp-uniform weights
    const int ng = t & 31;        // points 4ng..4ng+3 and 128+4ng..+3
    const int o0 = og * 8;

    unsigned long long acc[8][4];
    #pragma unroll
    for (int o = 0; o < 8; o++) {
        float bb = biasS[o0 + o];
        unsigned long long bp = pack2(bb, bb);
        acc[o][0] = bp; acc[o][1] = bp; acc[o][2] = bp; acc[o][3] = bp;
    }

    #pragma unroll
    for (int c = 0; c < CDIM; c++) {
        const float* wr = wS + c * CDIM + o0;      // scalar broadcast loads
        unsigned long long w0 = pack2(wr[0], wr[0]);
        unsigned long long w1 = pack2(wr[1], wr[1]);
        unsigned long long w2 = pack2(wr[2], wr[2]);
        unsigned long long w3 = pack2(wr[3], wr[3]);
        unsigned long long w4 = pack2(wr[4], wr[4]);
        unsigned long long w5 = pack2(wr[5], wr[5]);
        unsigned long long w6 = pack2(wr[6], wr[6]);
        unsigned long long w7 = pack2(wr[7], wr[7]);

        const float* arow = aggS + c * ASTR + 4 * ng;
        const ulonglong2 a0 = *reinterpret_cast<const ulonglong2*>(arow);        // pts 4ng..+3
        const ulonglong2 a1 = *reinterpret_cast<const ulonglong2*>(arow + 128);  // pts 128+4ng..+3

        acc[0][0] = fma2(w0, a0.x, acc[0][0]);
        acc[0][1] = fma2(w0, a0.y, acc[0][1]);
        acc[0][2] = fma2(w0, a1.x, acc[0][2]);
        acc[0][3] = fma2(w0, a1.y, acc[0][3]);
        acc[1][0] = fma2(w1, a0.x, acc[1][0]);
        acc[1][1] = fma2(w1, a0.y, acc[1][1]);
        acc[1][2] = fma2(w1, a1.x, acc[1][2]);
        acc[1][3] = fma2(w1, a1.y, acc[1][3]);
        acc[2][0] = fma2(w2, a0.x, acc[2][0]);
        acc[2][1] = fma2(w2, a0.y, acc[2][1]);
        acc[2][2] = fma2(w2, a1.x, acc[2][2]);
        acc[2][3] = fma2(w2, a1.y, acc[2][3]);
        acc[3][0] = fma2(w3, a0.x, acc[3][0]);
        acc[3][1] = fma2(w3, a0.y, acc[3][1]);
        acc[3][2] = fma2(w3, a1.x, acc[3][2]);
        acc[3][3] = fma2(w3, a1.y, acc[3][3]);
        acc[4][0] = fma2(w4, a0.x, acc[4][0]);
        acc[4][1] = fma2(w4, a0.y, acc[4][1]);
        acc[4][2] = fma2(w4, a1.x, acc[4][2]);
        acc[4][3] = fma2(w4, a1.y, acc[4][3]);
        acc[5][0] = fma2(w5, a0.x, acc[5][0]);
        acc[5][1] = fma2(w5, a0.y, acc[5][1]);
        acc[5][2] = fma2(w5, a1.x, acc[5][2]);
        acc[5][3] = fma2(w5, a1.y, acc[5][3]);
        acc[6][0] = fma2(w6, a0.x, acc[6][0]);
        acc[6][1] = fma2(w6, a0.y, acc[6][1]);
        acc[6][2] = fma2(w6, a1.x, acc[6][2]);
        acc[6][3] = fma2(w6, a1.y, acc[6][3]);
        acc[7][0] = fma2(w7, a0.x, acc[7][0]);
        acc[7][1] = fma2(w7, a0.y, acc[7][1]);
        acc[7][2] = fma2(w7, a1.x, acc[7][2]);
        acc[7][3] = fma2(w7, a1.y, acc[7][3]);
    }

    // ---- Epilogue: relu + coalesced float4 stores ----
    float* outb = out + (size_t)b * CDIM * PDIM + ptile;
    #pragma unroll
    for (int o = 0; o < 8; o++) {
        float* rowp = outb + (size_t)(o0 + o) * PDIM;
        float x0, x1, x2, x3;

        unpack2(acc[o][0], x0, x1);
        unpack2(acc[o][1], x2, x3);
        *reinterpret_cast<float4*>(rowp + 4 * ng) =
            make_float4(fmaxf(x0, 0.f), fmaxf(x1, 0.f),
                        fmaxf(x2, 0.f), fmaxf(x3, 0.f));

        unpack2(acc[o][2], x0, x1);
        unpack2(acc[o][3], x2, x3);
        *reinterpret_cast<float4*>(rowp + 128 + 4 * ng) =
            make_float4(fmaxf(x0, 0.f), fmaxf(x1, 0.f),
                        fmaxf(x2, 0.f), fmaxf(x3, 0.f));
    }
}

// ---------------------------------------------------------------------------
// Launch: single kernel (fold is computed in-block).
// ---------------------------------------------------------------------------
extern "C" void kernel_launch(void* const* d_in, const int* in_sizes, int n_in,
                              void* d_out, int out_size) {
    const float* feat_a = (const float*)d_in[0];
    const float* feat_b = (const float*)d_in[1];
    const int* assign_a = (const int*)d_in[2];
    const int* assign_b = (const int*)d_in[3];
    const float* bn1_gamma = (const float*)d_in[4];
    const float* bn1_beta = (const float*)d_in[5];
    const float* bn1_mean = (const float*)d_in[6];
    const float* bn1_var = (const float*)d_in[7];
    const float* conv_w = (const float*)d_in[8];
    const float* bn2_gamma = (const float*)d_in[9];
    const float* bn2_beta = (const float*)d_in[10];
    const float* bn2_mean = (const float*)d_in[11];
    const float* bn2_var = (const float*)d_in[12];
    float* out = (float*)d_out;

    dim3 grid(PDIM / TILE_P, BDIM);
    feynnet_kernel<<<grid, TPB>>>(feat_a, feat_b, assign_a, assign_b,
                                  conv_w,
                                  bn1_gamma, bn1_beta, bn1_mean, bn1_var,
                                  bn2_gamma, bn2_beta, bn2_mean, bn2_var,
                                  out);
}